// round 8
// baseline (speedup 1.0000x reference)
#include <cuda_runtime.h>
#include <cuda_bf16.h>
#include <math.h>
#include <stdint.h>

#define NN 30000
#define EE 480000
#define ET (EE + NN)
#define FIN 4096
#define HC 512
#define HEADS 4
#define HID 128
#define CLS 6

// ---------------- scratch (static device globals) ---------------------------
__device__ float    g_h1[(size_t)NN * HC];
__device__ float    g_out1[(size_t)NN * HC];
__device__ float    g_w1t[(size_t)HC * FIN];   // W1^T, tf32-rounded, K-major
__device__ float    g_as1[NN * HEADS];
__device__ float    g_ad1[NN * HEADS];
__device__ float    g_h2[NN * CLS];
__device__ float    g_as2[NN];
__device__ float    g_ad2[NN];
__device__ int      g_deg[NN];
__device__ int      g_off[NN + 1];
__device__ int      g_pos[NN];
__device__ int      g_esrc[ET];

__device__ __forceinline__ float lrelu(float v) { return v > 0.f ? v : 0.2f * v; }
__device__ __forceinline__ unsigned tf32rna(float f) {
    unsigned u = __float_as_uint(f);
    asm("cvt.rna.tf32.f32 %0, %0;" : "+r"(u));
    return u;
}
__device__ __forceinline__ void edge_sd(const int* __restrict__ ei, int e,
                                        int& s, int& d) {
    if (e < EE) { s = ei[e]; d = ei[EE + e]; } else { s = d = e - EE; }
}
__device__ __forceinline__ uint32_t smem_u32(const void* p) {
    uint32_t a;
    asm("{ .reg .u64 t; cvta.to.shared.u64 t, %1; cvt.u32.u64 %0, t; }"
        : "=r"(a) : "l"(p));
    return a;
}
__device__ __forceinline__ void cp16(uint32_t saddr, const void* g, int bytes) {
    asm volatile("cp.async.ca.shared.global [%0], [%1], 16, %2;"
                 :: "r"(saddr), "l"(g), "r"(bytes));
}

// ---------------- CSR build --------------------------------------------------
__global__ void zero_deg_kernel() {
    int i = blockIdx.x * blockDim.x + threadIdx.x;
    if (i < NN) g_deg[i] = 0;
}
__global__ void count_kernel(const int* __restrict__ ei) {
    int e = blockIdx.x * blockDim.x + threadIdx.x;
    if (e >= ET) return;
    int s, d; edge_sd(ei, e, s, d);
    atomicAdd(&g_deg[d], 1);
}
__global__ void scan_kernel() {
    __shared__ int partial[1024];
    const int t = threadIdx.x;
    const int CH = (NN + 1023) / 1024;
    const int base = t * CH;
    int sum = 0;
    for (int c = 0; c < CH; c++) { int i = base + c; if (i < NN) sum += g_deg[i]; }
    partial[t] = sum;
    __syncthreads();
    for (int off = 1; off < 1024; off <<= 1) {
        int v = (t >= off) ? partial[t - off] : 0;
        __syncthreads();
        partial[t] += v;
        __syncthreads();
    }
    int acc = partial[t] - sum;
    for (int c = 0; c < CH; c++) {
        int i = base + c;
        if (i < NN) { g_off[i] = acc; g_pos[i] = acc; acc += g_deg[i]; }
    }
    if (t == 0) g_off[NN] = ET;
}
__global__ void scatter_kernel(const int* __restrict__ ei) {
    int e = blockIdx.x * blockDim.x + threadIdx.x;
    if (e >= ET) return;
    int s, d; edge_sd(ei, e, s, d);
    int p = atomicAdd(&g_pos[d], 1);
    g_esrc[p] = s;
}

// ---------- transpose + tf32-round W1 (32x32 shared tiles, coalesced) -------
__global__ __launch_bounds__(256) void w1t_kernel(const float* __restrict__ W1) {
    __shared__ float tile[32][33];
    const int k0 = blockIdx.y * 32;
    const int n0 = blockIdx.x * 32;
    const int tx = threadIdx.x & 31;
    const int ty = threadIdx.x >> 5;
#pragma unroll
    for (int r = 0; r < 4; r++) {
        int k = k0 + ty + r * 8;
        tile[ty + r * 8][tx] = __uint_as_float(tf32rna(W1[(size_t)k * HC + n0 + tx]));
    }
    __syncthreads();
#pragma unroll
    for (int r = 0; r < 4; r++) {
        int n = n0 + ty + r * 8;
        g_w1t[(size_t)n * FIN + k0 + tx] = tile[tx][ty + r * 8];
    }
}

// ---------------- GEMM1 (mma.sync tf32): h1 = x @ W1 ------------------------
// CTA tile 128x128, 128 threads (2x2 warps of 64x64), BK=32, 3-stage,
// 110.6 KB smem -> 2 CTAs/SM for cross-CTA latency hiding.
#define BM 128
#define BN 128
#define BK2 32
#define ASTR 36
#define A_STAGE (BM * ASTR)
#define B_STAGE (BN * ASTR)
#define SMEM_BYTES (3 * (A_STAGE + B_STAGE) * 4)   // 110592

__global__ __launch_bounds__(128, 2) void gemm1_tc(const float* __restrict__ A) {
    extern __shared__ float sm[];
    float* Asm = sm;
    float* Bsm = sm + 3 * A_STAGE;
    const int t    = threadIdx.x;           // 0..127
    const int m0   = blockIdx.y * BM;
    const int n0   = blockIdx.x * BN;
    const int wid  = t >> 5;                // 0..3
    const int lane = t & 31;
    const int gid  = lane >> 2;
    const int tid4 = lane & 3;
    const int wm   = (wid >> 1) * 64;
    const int wn   = (wid & 1) * 64;

    float acc[4][8][4];
#pragma unroll
    for (int i = 0; i < 4; i++)
#pragma unroll
        for (int j = 0; j < 8; j++)
#pragma unroll
            for (int r = 0; r < 4; r++) acc[i][j][r] = 0.f;

    auto load_stage = [&](int s, int k0) {
        uint32_t ab = smem_u32(Asm + s * A_STAGE);
        uint32_t bb = smem_u32(Bsm + s * B_STAGE);
#pragma unroll
        for (int j = 0; j < 8; j++) {               // A: 1024 float4 / 128 thr
            int idx = j * 128 + t;
            int row = idx >> 3, c4 = (idx & 7) << 2;
            int gr = m0 + row;
            cp16(ab + (row * ASTR + c4) * 4,
                 A + (size_t)gr * FIN + k0 + c4, gr < NN ? 16 : 0);
        }
#pragma unroll
        for (int j = 0; j < 8; j++) {               // B: 1024 float4 / 128 thr
            int idx = j * 128 + t;
            int row = idx >> 3, c4 = (idx & 7) << 2;
            cp16(bb + (row * ASTR + c4) * 4,
                 g_w1t + (size_t)(n0 + row) * FIN + k0 + c4, 16);
        }
        asm volatile("cp.async.commit_group;");
    };

    load_stage(0, 0);
    load_stage(1, BK2);

    const int NT = FIN / BK2;          // 128
    for (int kt = 0; kt < NT; kt++) {
        if (kt + 1 < NT) asm volatile("cp.async.wait_group 1;");
        else             asm volatile("cp.async.wait_group 0;");
        __syncthreads();
        const int s = kt % 3;
        const float* as = Asm + s * A_STAGE;
        const float* bs = Bsm + s * B_STAGE;

#pragma unroll
        for (int kk = 0; kk < BK2; kk += 8) {
            unsigned af[4][4], bf[8][2];
#pragma unroll
            for (int mt = 0; mt < 4; mt++) {
                int r = wm + mt * 16 + gid;
                af[mt][0] = tf32rna(as[r * ASTR + kk + tid4]);
                af[mt][1] = tf32rna(as[(r + 8) * ASTR + kk + tid4]);
                af[mt][2] = tf32rna(as[r * ASTR + kk + tid4 + 4]);
                af[mt][3] = tf32rna(as[(r + 8) * ASTR + kk + tid4 + 4]);
            }
#pragma unroll
            for (int nt = 0; nt < 8; nt++) {
                int c = wn + nt * 8 + gid;
                bf[nt][0] = __float_as_uint(bs[c * ASTR + kk + tid4]);
                bf[nt][1] = __float_as_uint(bs[c * ASTR + kk + tid4 + 4]);
            }
#pragma unroll
            for (int mt = 0; mt < 4; mt++)
#pragma unroll
                for (int nt = 0; nt < 8; nt++) {
                    asm volatile(
                        "mma.sync.aligned.m16n8k8.row.col.f32.tf32.tf32.f32 "
                        "{%0,%1,%2,%3}, {%4,%5,%6,%7}, {%8,%9}, {%0,%1,%2,%3};"
                        : "+f"(acc[mt][nt][0]), "+f"(acc[mt][nt][1]),
                          "+f"(acc[mt][nt][2]), "+f"(acc[mt][nt][3])
                        : "r"(af[mt][0]), "r"(af[mt][1]),
                          "r"(af[mt][2]), "r"(af[mt][3]),
                          "r"(bf[nt][0]), "r"(bf[nt][1]));
                }
        }
        if (kt + 2 < NT) load_stage((kt + 2) % 3, (kt + 2) * BK2);
    }

#pragma unroll
    for (int mt = 0; mt < 4; mt++) {
        int r1 = m0 + wm + mt * 16 + gid;
        int r2 = r1 + 8;
#pragma unroll
        for (int nt = 0; nt < 8; nt++) {
            int c = n0 + wn + nt * 8 + tid4 * 2;
            if (r1 < NN) *(float2*)(g_h1 + (size_t)r1 * HC + c) =
                make_float2(acc[mt][nt][0], acc[mt][nt][1]);
            if (r2 < NN) *(float2*)(g_h1 + (size_t)r2 * HC + c) =
                make_float2(acc[mt][nt][2], acc[mt][nt][3]);
        }
    }
}

// ---------------- per-node attention logits (layer 1) ------------------------
__global__ void alpha1_kernel(const float* __restrict__ asrc,
                              const float* __restrict__ adst) {
    int warp = (blockIdx.x * blockDim.x + threadIdx.x) >> 5;
    int lane = threadIdx.x & 31;
    if (warp >= NN) return;
    const float* row = g_h1 + (size_t)warp * HC;
    float ps[HEADS], pd[HEADS];
#pragma unroll
    for (int h = 0; h < HEADS; h++) { ps[h] = 0.f; pd[h] = 0.f; }
#pragma unroll
    for (int h = 0; h < HEADS; h++)
#pragma unroll
        for (int j = 0; j < 4; j++) {
            int idx = (h * 4 + j) * 32 + lane;
            float v = row[idx];
            ps[h] += v * asrc[idx];
            pd[h] += v * adst[idx];
        }
#pragma unroll
    for (int off = 16; off; off >>= 1)
#pragma unroll
        for (int h = 0; h < HEADS; h++) {
            ps[h] += __shfl_xor_sync(0xffffffffu, ps[h], off);
            pd[h] += __shfl_xor_sync(0xffffffffu, pd[h], off);
        }
    if (lane == 0)
#pragma unroll
        for (int h = 0; h < HEADS; h++) {
            g_as1[warp * HEADS + h] = ps[h];
            g_ad1[warp * HEADS + h] = pd[h];
        }
}

// ------- fused layer-1 softmax + aggregate: 4 warps per dst node (1 head) ---
__global__ __launch_bounds__(256) void fused_agg1() {
    int gw   = (blockIdx.x * blockDim.x + threadIdx.x) >> 5;
    int lane = threadIdx.x & 31;
    int d    = gw >> 2;
    int h    = gw & 3;
    if (d >= NN) return;
    const int beg = g_off[d], end = g_off[d + 1];
    const int deg = end - beg;
    const float ad = g_ad1[d * 4 + h];
    const float4* hbase = (const float4*)g_h1;

    float den;
    float4 a = {0.f, 0.f, 0.f, 0.f};

    if (deg <= 32) {
        int   s_l = (lane < deg) ? g_esrc[beg + lane] : 0;
        float e_l = (lane < deg) ? lrelu(g_as1[s_l * 4 + h] + ad) : -1e30f;
        float m = e_l;
#pragma unroll
        for (int off = 16; off; off >>= 1)
            m = fmaxf(m, __shfl_xor_sync(0xffffffffu, m, off));
        float w_l = (lane < deg) ? __expf(e_l - m) : 0.f;
        den = w_l;
#pragma unroll
        for (int off = 16; off; off >>= 1)
            den += __shfl_xor_sync(0xffffffffu, den, off);
#pragma unroll 8
        for (int j = 0; j < deg; j++) {
            float w = __shfl_sync(0xffffffffu, w_l, j);
            int   s = __shfl_sync(0xffffffffu, s_l, j);
            float4 v = hbase[(size_t)s * 128 + h * 32 + lane];
            a.x += w * v.x; a.y += w * v.y; a.z += w * v.z; a.w += w * v.w;
        }
    } else {
        float m = -1e30f;
        for (int i = beg + lane; i < end; i += 32)
            m = fmaxf(m, lrelu(g_as1[g_esrc[i] * 4 + h] + ad));
#pragma unroll
        for (int off = 16; off; off >>= 1)
            m = fmaxf(m, __shfl_xor_sync(0xffffffffu, m, off));
        den = 0.f;
        for (int base = beg; base < end; base += 32) {
            int   idx = base + lane;
            int   s_l = (idx < end) ? g_esrc[idx] : 0;
            float w_l = (idx < end)
                      ? __expf(lrelu(g_as1[s_l * 4 + h] + ad) - m) : 0.f;
            den += w_l;
            int n = min(32, end - base);
#pragma unroll 8
            for (int j = 0; j < n; j++) {
                float w = __shfl_sync(0xffffffffu, w_l, j);
                int   s = __shfl_sync(0xffffffffu, s_l, j);
                float4 v = hbase[(size_t)s * 128 + h * 32 + lane];
                a.x += w * v.x; a.y += w * v.y; a.z += w * v.z; a.w += w * v.w;
            }
        }
#pragma unroll
        for (int off = 16; off; off >>= 1)
            den += __shfl_xor_sync(0xffffffffu, den, off);
    }
    const float r = 1.f / den;
    a.x *= r; a.y *= r; a.z *= r; a.w *= r;
    ((float4*)g_out1)[(size_t)d * 128 + h * 32 + lane] = a;
}

// --------- ELU + tiny GEMM2 (512x6) + layer-2 logits ------------------------
__global__ void elu_gemm2_kernel(const float* __restrict__ b1,
                                 const float* __restrict__ W2,
                                 const float* __restrict__ asrc2,
                                 const float* __restrict__ adst2) {
    int warp = (blockIdx.x * blockDim.x + threadIdx.x) >> 5;
    int lane = threadIdx.x & 31;
    if (warp >= NN) return;
    const float* row = g_out1 + (size_t)warp * HC;
    float acc[CLS];
#pragma unroll
    for (int c = 0; c < CLS; c++) acc[c] = 0.f;
#pragma unroll
    for (int i = 0; i < 16; i++) {
        int k = lane + 32 * i;
        float a = row[k] + b1[k];
        a = a > 0.f ? a : (__expf(a) - 1.f);
#pragma unroll
        for (int c = 0; c < CLS; c++) acc[c] += a * W2[k * CLS + c];
    }
#pragma unroll
    for (int off = 16; off; off >>= 1)
#pragma unroll
        for (int c = 0; c < CLS; c++)
            acc[c] += __shfl_xor_sync(0xffffffffu, acc[c], off);
    if (lane == 0) {
        float s2 = 0.f, d2 = 0.f;
#pragma unroll
        for (int c = 0; c < CLS; c++) {
            g_h2[warp * CLS + c] = acc[c];
            s2 += acc[c] * asrc2[c];
            d2 += acc[c] * adst2[c];
        }
        g_as2[warp] = s2;
        g_ad2[warp] = d2;
    }
}

// ------------- fused layer-2 softmax + aggregate ----------------------------
__global__ __launch_bounds__(256) void fused_agg2(const float* __restrict__ b2,
                                                  float* __restrict__ out) {
    int d    = (blockIdx.x * blockDim.x + threadIdx.x) >> 5;
    int lane = threadIdx.x & 31;
    if (d >= NN) return;
    const int beg = g_off[d], end = g_off[d + 1];
    const float ad = g_ad2[d];

    float m = -1e30f;
    for (int i = beg + lane; i < end; i += 32)
        m = fmaxf(m, lrelu(g_as2[g_esrc[i]] + ad));
#pragma unroll
    for (int off = 16; off; off >>= 1)
        m = fmaxf(m, __shfl_xor_sync(0xffffffffu, m, off));

    float den = 0.f;
    float acc[CLS];
#pragma unroll
    for (int c = 0; c < CLS; c++) acc[c] = 0.f;
    for (int i = beg + lane; i < end; i += 32) {
        int s = g_esrc[i];
        float w = __expf(lrelu(g_as2[s] + ad) - m);
        den += w;
#pragma unroll
        for (int c = 0; c < CLS; c++) acc[c] += w * g_h2[s * CLS + c];
    }
#pragma unroll
    for (int off = 16; off; off >>= 1) {
        den += __shfl_xor_sync(0xffffffffu, den, off);
#pragma unroll
        for (int c = 0; c < CLS; c++)
            acc[c] += __shfl_xor_sync(0xffffffffu, acc[c], off);
    }
    if (lane == 0) {
        float rden = 1.f / den;
#pragma unroll
        for (int c = 0; c < CLS; c++)
            out[d * CLS + c] = acc[c] * rden + b2[c];
    }
}

// ---------------- launch ----------------------------------------------------
extern "C" void kernel_launch(void* const* d_in, const int* in_sizes, int n_in,
                              void* d_out, int out_size) {
    const float* x     = (const float*)d_in[0];
    const int*   ei    = (const int*)d_in[1];
    const float* W1    = (const float*)d_in[2];
    const float* asrc1 = (const float*)d_in[3];
    const float* adst1 = (const float*)d_in[4];
    const float* b1    = (const float*)d_in[5];
    const float* W2    = (const float*)d_in[6];
    const float* asrc2 = (const float*)d_in[7];
    const float* adst2 = (const float*)d_in[8];
    const float* b2    = (const float*)d_in[9];
    float* out = (float*)d_out;

    static cudaStream_t s2 = nullptr;
    static cudaEvent_t  e1 = nullptr, e2 = nullptr;
    if (!s2) {
        cudaStreamCreateWithFlags(&s2, cudaStreamNonBlocking);
        cudaEventCreateWithFlags(&e1, cudaEventDisableTiming);
        cudaEventCreateWithFlags(&e2, cudaEventDisableTiming);
        cudaFuncSetAttribute(gemm1_tc,
                             cudaFuncAttributeMaxDynamicSharedMemorySize, SMEM_BYTES);
    }

    // fork: CSR build on side stream, overlapped with w1t + GEMM
    cudaEventRecord(e1, 0);
    cudaStreamWaitEvent(s2, e1, 0);
    zero_deg_kernel<<<(NN + 255) / 256, 256, 0, s2>>>();
    count_kernel<<<(ET + 255) / 256, 256, 0, s2>>>(ei);
    scan_kernel<<<1, 1024, 0, s2>>>();
    scatter_kernel<<<(ET + 255) / 256, 256, 0, s2>>>(ei);
    cudaEventRecord(e2, s2);

    w1t_kernel<<<dim3(HC / 32, FIN / 32), 256>>>(W1);
    gemm1_tc<<<dim3(HC / BN, (NN + BM - 1) / BM), 128, SMEM_BYTES>>>(x);
    alpha1_kernel<<<(NN * 32 + 255) / 256, 256>>>(asrc1, adst1);

    // join: aggregation needs CSR + logits
    cudaStreamWaitEvent(0, e2, 0);
    fused_agg1<<<(NN * 128 + 255) / 256, 256>>>();
    elu_gemm2_kernel<<<(NN * 32 + 255) / 256, 256>>>(b1, W2, asrc2, adst2);
    fused_agg2<<<(NN * 32 + 255) / 256, 256>>>(b2, out);
}

// round 9
// speedup vs baseline: 1.0793x; 1.0793x over previous
#include <cuda_runtime.h>
#include <cuda_bf16.h>
#include <math.h>
#include <stdint.h>

#define NN 30000
#define EE 480000
#define ET (EE + NN)
#define FIN 4096
#define HC 512
#define HEADS 4
#define HID 128
#define CLS 6

// ---------------- scratch (static device globals) ---------------------------
__device__ float    g_h1[(size_t)NN * HC];
__device__ float    g_w1t[(size_t)HC * FIN];   // W1^T, tf32-rounded, K-major
__device__ float    g_as1[NN * HEADS];
__device__ float    g_ad1[NN * HEADS];
__device__ float    g_h2[NN * CLS];
__device__ float    g_as2[NN];
__device__ float    g_ad2[NN];
__device__ int      g_deg[NN];
__device__ int      g_off[NN + 1];
__device__ int      g_pos[NN];
__device__ int      g_esrc[ET];

__device__ __forceinline__ float lrelu(float v) { return v > 0.f ? v : 0.2f * v; }
__device__ __forceinline__ unsigned tf32rna(float f) {
    unsigned u = __float_as_uint(f);
    asm("cvt.rna.tf32.f32 %0, %0;" : "+r"(u));
    return u;
}
__device__ __forceinline__ void edge_sd(const int* __restrict__ ei, int e,
                                        int& s, int& d) {
    if (e < EE) { s = ei[e]; d = ei[EE + e]; } else { s = d = e - EE; }
}
__device__ __forceinline__ uint32_t smem_u32(const void* p) {
    uint32_t a;
    asm("{ .reg .u64 t; cvta.to.shared.u64 t, %1; cvt.u32.u64 %0, t; }"
        : "=r"(a) : "l"(p));
    return a;
}
__device__ __forceinline__ void cp16(uint32_t saddr, const void* g, int bytes) {
    asm volatile("cp.async.ca.shared.global [%0], [%1], 16, %2;"
                 :: "r"(saddr), "l"(g), "r"(bytes));
}

// ---------------- CSR build --------------------------------------------------
__global__ void zero_deg_kernel() {
    int i = blockIdx.x * blockDim.x + threadIdx.x;
    if (i < NN) g_deg[i] = 0;
}
__global__ void count_kernel(const int* __restrict__ ei) {
    int e = blockIdx.x * blockDim.x + threadIdx.x;
    if (e >= ET) return;
    int s, d; edge_sd(ei, e, s, d);
    atomicAdd(&g_deg[d], 1);
}
__global__ void scan_kernel() {
    __shared__ int partial[1024];
    const int t = threadIdx.x;
    const int CH = (NN + 1023) / 1024;
    const int base = t * CH;
    int sum = 0;
    for (int c = 0; c < CH; c++) { int i = base + c; if (i < NN) sum += g_deg[i]; }
    partial[t] = sum;
    __syncthreads();
    for (int off = 1; off < 1024; off <<= 1) {
        int v = (t >= off) ? partial[t - off] : 0;
        __syncthreads();
        partial[t] += v;
        __syncthreads();
    }
    int acc = partial[t] - sum;
    for (int c = 0; c < CH; c++) {
        int i = base + c;
        if (i < NN) { g_off[i] = acc; g_pos[i] = acc; acc += g_deg[i]; }
    }
    if (t == 0) g_off[NN] = ET;
}
__global__ void scatter_kernel(const int* __restrict__ ei) {
    int e = blockIdx.x * blockDim.x + threadIdx.x;
    if (e >= ET) return;
    int s, d; edge_sd(ei, e, s, d);
    int p = atomicAdd(&g_pos[d], 1);
    g_esrc[p] = s;
}

// ----- zero per-launch accumulators (alpha1 targets + h2) --------------------
__global__ void zero_acc_kernel() {
    int i = blockIdx.x * blockDim.x + threadIdx.x;
    if (i < NN * HEADS) { g_as1[i] = 0.f; g_ad1[i] = 0.f; }
    if (i < NN * CLS)   g_h2[i] = 0.f;
}

// ---------- transpose + tf32-round W1 (32x32 shared tiles, coalesced) -------
__global__ __launch_bounds__(256) void w1t_kernel(const float* __restrict__ W1) {
    __shared__ float tile[32][33];
    const int k0 = blockIdx.y * 32;
    const int n0 = blockIdx.x * 32;
    const int tx = threadIdx.x & 31;
    const int ty = threadIdx.x >> 5;
#pragma unroll
    for (int r = 0; r < 4; r++) {
        int k = k0 + ty + r * 8;
        tile[ty + r * 8][tx] = __uint_as_float(tf32rna(W1[(size_t)k * HC + n0 + tx]));
    }
    __syncthreads();
#pragma unroll
    for (int r = 0; r < 4; r++) {
        int n = n0 + ty + r * 8;
        g_w1t[(size_t)n * FIN + k0 + tx] = tile[tx][ty + r * 8];
    }
}

// ---------------- GEMM1 (mma.sync tf32): h1 = x @ W1 + fused alpha ----------
#define BM 128
#define BN 256
#define BK2 32
#define ASTR 36
#define A_STAGE (BM * ASTR)
#define B_STAGE (BN * ASTR)
#define SMEM_BYTES (3 * (A_STAGE + B_STAGE) * 4)

__global__ __launch_bounds__(256, 1) void gemm1_tc(const float* __restrict__ A,
                                                   const float* __restrict__ asrc,
                                                   const float* __restrict__ adst) {
    extern __shared__ float sm[];
    float* Asm = sm;
    float* Bsm = sm + 3 * A_STAGE;
    const int t    = threadIdx.x;
    const int m0   = blockIdx.y * BM;
    const int n0   = blockIdx.x * BN;
    const int wid  = t >> 5;
    const int lane = t & 31;
    const int gid  = lane >> 2;
    const int tid4 = lane & 3;
    const int wm   = (wid >> 2) * 64;
    const int wn   = (wid & 3) * 64;

    float acc[4][8][4];
#pragma unroll
    for (int i = 0; i < 4; i++)
#pragma unroll
        for (int j = 0; j < 8; j++)
#pragma unroll
            for (int r = 0; r < 4; r++) acc[i][j][r] = 0.f;

    auto load_stage = [&](int s, int k0) {
        uint32_t ab = smem_u32(Asm + s * A_STAGE);
        uint32_t bb = smem_u32(Bsm + s * B_STAGE);
#pragma unroll
        for (int j = 0; j < 4; j++) {
            int idx = j * 256 + t;
            int row = idx >> 3, c4 = (idx & 7) << 2;
            int gr = m0 + row;
            cp16(ab + (row * ASTR + c4) * 4,
                 A + (size_t)gr * FIN + k0 + c4, gr < NN ? 16 : 0);
        }
#pragma unroll
        for (int j = 0; j < 8; j++) {
            int idx = j * 256 + t;
            int row = idx >> 3, c4 = (idx & 7) << 2;
            cp16(bb + (row * ASTR + c4) * 4,
                 g_w1t + (size_t)(n0 + row) * FIN + k0 + c4, 16);
        }
        asm volatile("cp.async.commit_group;");
    };

    load_stage(0, 0);
    load_stage(1, BK2);

    const int NT = FIN / BK2;
    for (int kt = 0; kt < NT; kt++) {
        if (kt + 1 < NT) asm volatile("cp.async.wait_group 1;");
        else             asm volatile("cp.async.wait_group 0;");
        __syncthreads();
        const int s = kt % 3;
        const float* as = Asm + s * A_STAGE;
        const float* bs = Bsm + s * B_STAGE;

#pragma unroll
        for (int kk = 0; kk < BK2; kk += 8) {
            unsigned af[4][4], bf[8][2];
#pragma unroll
            for (int mt = 0; mt < 4; mt++) {
                int r = wm + mt * 16 + gid;
                af[mt][0] = tf32rna(as[r * ASTR + kk + tid4]);
                af[mt][1] = tf32rna(as[(r + 8) * ASTR + kk + tid4]);
                af[mt][2] = tf32rna(as[r * ASTR + kk + tid4 + 4]);
                af[mt][3] = tf32rna(as[(r + 8) * ASTR + kk + tid4 + 4]);
            }
#pragma unroll
            for (int nt = 0; nt < 8; nt++) {
                int c = wn + nt * 8 + gid;
                bf[nt][0] = __float_as_uint(bs[c * ASTR + kk + tid4]);
                bf[nt][1] = __float_as_uint(bs[c * ASTR + kk + tid4 + 4]);
            }
#pragma unroll
            for (int mt = 0; mt < 4; mt++)
#pragma unroll
                for (int nt = 0; nt < 8; nt++) {
                    asm volatile(
                        "mma.sync.aligned.m16n8k8.row.col.f32.tf32.tf32.f32 "
                        "{%0,%1,%2,%3}, {%4,%5,%6,%7}, {%8,%9}, {%0,%1,%2,%3};"
                        : "+f"(acc[mt][nt][0]), "+f"(acc[mt][nt][1]),
                          "+f"(acc[mt][nt][2]), "+f"(acc[mt][nt][3])
                        : "r"(af[mt][0]), "r"(af[mt][1]),
                          "r"(af[mt][2]), "r"(af[mt][3]),
                          "r"(bf[nt][0]), "r"(bf[nt][1]));
                }
        }
        if (kt + 2 < NT) load_stage((kt + 2) % 3, (kt + 2) * BK2);
    }

    // ---- epilogue: store h1 tile + fused alpha partials ----
    float ps1[4], pd1[4], ps2[4], pd2[4];
#pragma unroll
    for (int mt = 0; mt < 4; mt++) { ps1[mt]=0.f; pd1[mt]=0.f; ps2[mt]=0.f; pd2[mt]=0.f; }

#pragma unroll
    for (int mt = 0; mt < 4; mt++) {
        int r1 = m0 + wm + mt * 16 + gid;
        int r2 = r1 + 8;
#pragma unroll
        for (int nt = 0; nt < 8; nt++) {
            int c = n0 + wn + nt * 8 + tid4 * 2;
            float a0 = asrc[c], a1 = asrc[c + 1];
            float d0 = adst[c], d1 = adst[c + 1];
            ps1[mt] += acc[mt][nt][0] * a0 + acc[mt][nt][1] * a1;
            pd1[mt] += acc[mt][nt][0] * d0 + acc[mt][nt][1] * d1;
            ps2[mt] += acc[mt][nt][2] * a0 + acc[mt][nt][3] * a1;
            pd2[mt] += acc[mt][nt][2] * d0 + acc[mt][nt][3] * d1;
            if (r1 < NN) *(float2*)(g_h1 + (size_t)r1 * HC + c) =
                make_float2(acc[mt][nt][0], acc[mt][nt][1]);
            if (r2 < NN) *(float2*)(g_h1 + (size_t)r2 * HC + c) =
                make_float2(acc[mt][nt][2], acc[mt][nt][3]);
        }
    }
    // reduce over tid4 (lanes 0-3 of each quad hold disjoint columns)
#pragma unroll
    for (int mt = 0; mt < 4; mt++) {
#pragma unroll
        for (int off = 1; off <= 2; off <<= 1) {
            ps1[mt] += __shfl_xor_sync(0xffffffffu, ps1[mt], off);
            pd1[mt] += __shfl_xor_sync(0xffffffffu, pd1[mt], off);
            ps2[mt] += __shfl_xor_sync(0xffffffffu, ps2[mt], off);
            pd2[mt] += __shfl_xor_sync(0xffffffffu, pd2[mt], off);
        }
    }
    if (tid4 == 0) {
        const int head = (n0 + wn) >> 7;
#pragma unroll
        for (int mt = 0; mt < 4; mt++) {
            int r1 = m0 + wm + mt * 16 + gid;
            int r2 = r1 + 8;
            if (r1 < NN) {
                atomicAdd(&g_as1[r1 * HEADS + head], ps1[mt]);
                atomicAdd(&g_ad1[r1 * HEADS + head], pd1[mt]);
            }
            if (r2 < NN) {
                atomicAdd(&g_as1[r2 * HEADS + head], ps2[mt]);
                atomicAdd(&g_ad1[r2 * HEADS + head], pd2[mt]);
            }
        }
    }
}

// ------- fused layer-1 softmax + aggregate + ELU + GEMM2 partial ------------
// 4 warps per dst node (one head each). Result accumulated into g_h2 atomics.
__global__ __launch_bounds__(256) void fused_agg1(const float* __restrict__ b1,
                                                  const float* __restrict__ W2) {
    int gw   = (blockIdx.x * blockDim.x + threadIdx.x) >> 5;
    int lane = threadIdx.x & 31;
    int d    = gw >> 2;
    int h    = gw & 3;
    if (d >= NN) return;
    const int beg = g_off[d], end = g_off[d + 1];
    const int deg = end - beg;
    const float ad = g_ad1[d * 4 + h];
    const float4* hbase = (const float4*)g_h1;

    float den;
    float4 a = {0.f, 0.f, 0.f, 0.f};

    if (deg <= 32) {
        int   s_l = (lane < deg) ? g_esrc[beg + lane] : 0;
        float e_l = (lane < deg) ? lrelu(g_as1[s_l * 4 + h] + ad) : -1e30f;
        float m = e_l;
#pragma unroll
        for (int off = 16; off; off >>= 1)
            m = fmaxf(m, __shfl_xor_sync(0xffffffffu, m, off));
        float w_l = (lane < deg) ? __expf(e_l - m) : 0.f;
        den = w_l;
#pragma unroll
        for (int off = 16; off; off >>= 1)
            den += __shfl_xor_sync(0xffffffffu, den, off);
#pragma unroll 8
        for (int j = 0; j < deg; j++) {
            float w = __shfl_sync(0xffffffffu, w_l, j);
            int   s = __shfl_sync(0xffffffffu, s_l, j);
            float4 v = hbase[(size_t)s * 128 + h * 32 + lane];
            a.x += w * v.x; a.y += w * v.y; a.z += w * v.z; a.w += w * v.w;
        }
    } else {
        float m = -1e30f;
        for (int i = beg + lane; i < end; i += 32)
            m = fmaxf(m, lrelu(g_as1[g_esrc[i] * 4 + h] + ad));
#pragma unroll
        for (int off = 16; off; off >>= 1)
            m = fmaxf(m, __shfl_xor_sync(0xffffffffu, m, off));
        den = 0.f;
        for (int base = beg; base < end; base += 32) {
            int   idx = base + lane;
            int   s_l = (idx < end) ? g_esrc[idx] : 0;
            float w_l = (idx < end)
                      ? __expf(lrelu(g_as1[s_l * 4 + h] + ad) - m) : 0.f;
            den += w_l;
            int n = min(32, end - base);
#pragma unroll 8
            for (int j = 0; j < n; j++) {
                float w = __shfl_sync(0xffffffffu, w_l, j);
                int   s = __shfl_sync(0xffffffffu, s_l, j);
                float4 v = hbase[(size_t)s * 128 + h * 32 + lane];
                a.x += w * v.x; a.y += w * v.y; a.z += w * v.z; a.w += w * v.w;
            }
        }
#pragma unroll
        for (int off = 16; off; off >>= 1)
            den += __shfl_xor_sync(0xffffffffu, den, off);
    }
    const float r = 1.f / den;
    float vv[4] = {a.x * r, a.y * r, a.z * r, a.w * r};

    // ELU(. + b1) then 128x6 slice of GEMM2, reduced across warp
    float part[CLS];
#pragma unroll
    for (int c = 0; c < CLS; c++) part[c] = 0.f;
    const int kbase = h * 128 + lane * 4;
#pragma unroll
    for (int j = 0; j < 4; j++) {
        int k = kbase + j;
        float act = vv[j] + b1[k];
        act = act > 0.f ? act : (__expf(act) - 1.f);
#pragma unroll
        for (int c = 0; c < CLS; c++) part[c] += act * W2[k * CLS + c];
    }
#pragma unroll
    for (int off = 16; off; off >>= 1)
#pragma unroll
        for (int c = 0; c < CLS; c++)
            part[c] += __shfl_xor_sync(0xffffffffu, part[c], off);
    if (lane == 0)
#pragma unroll
        for (int c = 0; c < CLS; c++)
            atomicAdd(&g_h2[d * CLS + c], part[c]);
}

// ------------- layer-2 logits: one thread per node ---------------------------
__global__ void alpha2_kernel(const float* __restrict__ asrc2,
                              const float* __restrict__ adst2) {
    int i = blockIdx.x * blockDim.x + threadIdx.x;
    if (i >= NN) return;
    float s2 = 0.f, d2 = 0.f;
#pragma unroll
    for (int c = 0; c < CLS; c++) {
        float v = g_h2[i * CLS + c];
        s2 += v * asrc2[c];
        d2 += v * adst2[c];
    }
    g_as2[i] = s2;
    g_ad2[i] = d2;
}

// ------------- fused layer-2 softmax + aggregate ----------------------------
__global__ __launch_bounds__(256) void fused_agg2(const float* __restrict__ b2,
                                                  float* __restrict__ out) {
    int d    = (blockIdx.x * blockDim.x + threadIdx.x) >> 5;
    int lane = threadIdx.x & 31;
    if (d >= NN) return;
    const int beg = g_off[d], end = g_off[d + 1];
    const float ad = g_ad2[d];

    float m = -1e30f;
    for (int i = beg + lane; i < end; i += 32)
        m = fmaxf(m, lrelu(g_as2[g_esrc[i]] + ad));
#pragma unroll
    for (int off = 16; off; off >>= 1)
        m = fmaxf(m, __shfl_xor_sync(0xffffffffu, m, off));

    float den = 0.f;
    float acc[CLS];
#pragma unroll
    for (int c = 0; c < CLS; c++) acc[c] = 0.f;
    for (int i = beg + lane; i < end; i += 32) {
        int s = g_esrc[i];
        float w = __expf(lrelu(g_as2[s] + ad) - m);
        den += w;
#pragma unroll
        for (int c = 0; c < CLS; c++) acc[c] += w * g_h2[s * CLS + c];
    }
#pragma unroll
    for (int off = 16; off; off >>= 1) {
        den += __shfl_xor_sync(0xffffffffu, den, off);
#pragma unroll
        for (int c = 0; c < CLS; c++)
            acc[c] += __shfl_xor_sync(0xffffffffu, acc[c], off);
    }
    if (lane == 0) {
        float rden = 1.f / den;
#pragma unroll
        for (int c = 0; c < CLS; c++)
            out[d * CLS + c] = acc[c] * rden + b2[c];
    }
}

// ---------------- launch ----------------------------------------------------
extern "C" void kernel_launch(void* const* d_in, const int* in_sizes, int n_in,
                              void* d_out, int out_size) {
    const float* x     = (const float*)d_in[0];
    const int*   ei    = (const int*)d_in[1];
    const float* W1    = (const float*)d_in[2];
    const float* asrc1 = (const float*)d_in[3];
    const float* adst1 = (const float*)d_in[4];
    const float* b1    = (const float*)d_in[5];
    const float* W2    = (const float*)d_in[6];
    const float* asrc2 = (const float*)d_in[7];
    const float* adst2 = (const float*)d_in[8];
    const float* b2    = (const float*)d_in[9];
    float* out = (float*)d_out;

    static cudaStream_t s2 = nullptr;
    static cudaEvent_t  e1 = nullptr, e2 = nullptr;
    if (!s2) {
        cudaStreamCreateWithFlags(&s2, cudaStreamNonBlocking);
        cudaEventCreateWithFlags(&e1, cudaEventDisableTiming);
        cudaEventCreateWithFlags(&e2, cudaEventDisableTiming);
        cudaFuncSetAttribute(gemm1_tc,
                             cudaFuncAttributeMaxDynamicSharedMemorySize, SMEM_BYTES);
    }

    // fork: CSR build on side stream, overlapped with w1t + GEMM
    cudaEventRecord(e1, 0);
    cudaStreamWaitEvent(s2, e1, 0);
    zero_deg_kernel<<<(NN + 255) / 256, 256, 0, s2>>>();
    count_kernel<<<(ET + 255) / 256, 256, 0, s2>>>(ei);
    scan_kernel<<<1, 1024, 0, s2>>>();
    scatter_kernel<<<(ET + 255) / 256, 256, 0, s2>>>(ei);
    cudaEventRecord(e2, s2);

    zero_acc_kernel<<<(NN * CLS + 255) / 256, 256>>>();
    w1t_kernel<<<dim3(HC / 32, FIN / 32), 256>>>(W1);
    gemm1_tc<<<dim3(HC / BN, (NN + BM - 1) / BM), 256, SMEM_BYTES>>>(x, asrc1, adst1);

    // join: aggregation needs CSR + logits
    cudaStreamWaitEvent(0, e2, 0);
    fused_agg1<<<(NN * 128 + 255) / 256, 256>>>(b1, W2);
    alpha2_kernel<<<(NN + 255) / 256, 256>>>(asrc2, adst2);
    fused_agg2<<<(NN * 32 + 255) / 256, 256>>>(b2, out);
}

// round 10
// speedup vs baseline: 1.0832x; 1.0036x over previous
#include <cuda_runtime.h>
#include <cuda_bf16.h>
#include <math.h>
#include <stdint.h>

#define NN 30000
#define EE 480000
#define ET (EE + NN)
#define FIN 4096
#define HC 512
#define HEADS 4
#define HID 128
#define CLS 6

// ---------------- scratch (static device globals) ---------------------------
__device__ float    g_h1[(size_t)NN * HC];
__device__ float    g_w1t[(size_t)HC * FIN];   // W1^T, tf32-rounded, K-major
__device__ float    g_as1[NN * HEADS];
__device__ float    g_ad1[NN * HEADS];
__device__ float    g_h2[NN * CLS];
__device__ float    g_as2[NN];
__device__ float    g_ad2[NN];
__device__ int      g_deg[NN];
__device__ int      g_off[NN + 1];
__device__ int      g_pos[NN];
__device__ int      g_esrc[ET];

__device__ __forceinline__ float lrelu(float v) { return v > 0.f ? v : 0.2f * v; }
__device__ __forceinline__ unsigned tf32rna(float f) {
    unsigned u = __float_as_uint(f);
    asm("cvt.rna.tf32.f32 %0, %0;" : "+r"(u));
    return u;
}
__device__ __forceinline__ void edge_sd(const int* __restrict__ ei, int e,
                                        int& s, int& d) {
    if (e < EE) { s = ei[e]; d = ei[EE + e]; } else { s = d = e - EE; }
}
__device__ __forceinline__ uint32_t smem_u32(const void* p) {
    uint32_t a;
    asm("{ .reg .u64 t; cvta.to.shared.u64 t, %1; cvt.u32.u64 %0, t; }"
        : "=r"(a) : "l"(p));
    return a;
}
__device__ __forceinline__ void cp16(uint32_t saddr, const void* g, int bytes) {
    asm volatile("cp.async.ca.shared.global [%0], [%1], 16, %2;"
                 :: "r"(saddr), "l"(g), "r"(bytes));
}

// ---------------- CSR build --------------------------------------------------
__global__ void zero_deg_kernel() {
    int i = blockIdx.x * blockDim.x + threadIdx.x;
    if (i < NN) g_deg[i] = 0;
    if (i < NN * CLS) g_h2[i] = 0.f;     // also zero h2 accumulator (side stream)
}
__global__ void count_kernel(const int* __restrict__ ei) {
    int e = blockIdx.x * blockDim.x + threadIdx.x;
    if (e >= ET) return;
    int s, d; edge_sd(ei, e, s, d);
    atomicAdd(&g_deg[d], 1);
}
__global__ void scan_kernel() {
    __shared__ int partial[1024];
    const int t = threadIdx.x;
    const int CH = (NN + 1023) / 1024;
    const int base = t * CH;
    int sum = 0;
    for (int c = 0; c < CH; c++) { int i = base + c; if (i < NN) sum += g_deg[i]; }
    partial[t] = sum;
    __syncthreads();
    for (int off = 1; off < 1024; off <<= 1) {
        int v = (t >= off) ? partial[t - off] : 0;
        __syncthreads();
        partial[t] += v;
        __syncthreads();
    }
    int acc = partial[t] - sum;
    for (int c = 0; c < CH; c++) {
        int i = base + c;
        if (i < NN) { g_off[i] = acc; g_pos[i] = acc; acc += g_deg[i]; }
    }
    if (t == 0) g_off[NN] = ET;
}
__global__ void scatter_kernel(const int* __restrict__ ei) {
    int e = blockIdx.x * blockDim.x + threadIdx.x;
    if (e >= ET) return;
    int s, d; edge_sd(ei, e, s, d);
    int p = atomicAdd(&g_pos[d], 1);
    g_esrc[p] = s;
}

// ---------- transpose + tf32-round W1 (32x32 shared tiles, coalesced) -------
__global__ __launch_bounds__(256) void w1t_kernel(const float* __restrict__ W1) {
    __shared__ float tile[32][33];
    const int k0 = blockIdx.y * 32;
    const int n0 = blockIdx.x * 32;
    const int tx = threadIdx.x & 31;
    const int ty = threadIdx.x >> 5;
#pragma unroll
    for (int r = 0; r < 4; r++) {
        int k = k0 + ty + r * 8;
        tile[ty + r * 8][tx] = __uint_as_float(tf32rna(W1[(size_t)k * HC + n0 + tx]));
    }
    __syncthreads();
#pragma unroll
    for (int r = 0; r < 4; r++) {
        int n = n0 + ty + r * 8;
        g_w1t[(size_t)n * FIN + k0 + tx] = tile[tx][ty + r * 8];
    }
}

// ---------------- GEMM1 (mma.sync tf32): h1 = x @ W1 ------------------------
// CTA tile 128x256, BK=32, 3-stage cp.async pipeline, 8 warps, warp 64x64.
#define BM 128
#define BN 256
#define BK2 32
#define ASTR 36
#define A_STAGE (BM * ASTR)
#define B_STAGE (BN * ASTR)
#define SMEM_BYTES (3 * (A_STAGE + B_STAGE) * 4)

__global__ __launch_bounds__(256, 1) void gemm1_tc(const float* __restrict__ A) {
    extern __shared__ float sm[];
    float* Asm = sm;
    float* Bsm = sm + 3 * A_STAGE;
    const int t    = threadIdx.x;
    const int m0   = blockIdx.y * BM;
    const int n0   = blockIdx.x * BN;
    const int wid  = t >> 5;
    const int lane = t & 31;
    const int gid  = lane >> 2;
    const int tid4 = lane & 3;
    const int wm   = (wid >> 2) * 64;
    const int wn   = (wid & 3) * 64;

    float acc[4][8][4];
#pragma unroll
    for (int i = 0; i < 4; i++)
#pragma unroll
        for (int j = 0; j < 8; j++)
#pragma unroll
            for (int r = 0; r < 4; r++) acc[i][j][r] = 0.f;

    auto load_stage = [&](int s, int k0) {
        uint32_t ab = smem_u32(Asm + s * A_STAGE);
        uint32_t bb = smem_u32(Bsm + s * B_STAGE);
#pragma unroll
        for (int j = 0; j < 4; j++) {
            int idx = j * 256 + t;
            int row = idx >> 3, c4 = (idx & 7) << 2;
            int gr = m0 + row;
            cp16(ab + (row * ASTR + c4) * 4,
                 A + (size_t)gr * FIN + k0 + c4, gr < NN ? 16 : 0);
        }
#pragma unroll
        for (int j = 0; j < 8; j++) {
            int idx = j * 256 + t;
            int row = idx >> 3, c4 = (idx & 7) << 2;
            cp16(bb + (row * ASTR + c4) * 4,
                 g_w1t + (size_t)(n0 + row) * FIN + k0 + c4, 16);
        }
        asm volatile("cp.async.commit_group;");
    };

    load_stage(0, 0);
    load_stage(1, BK2);

    const int NT = FIN / BK2;
    for (int kt = 0; kt < NT; kt++) {
        if (kt + 1 < NT) asm volatile("cp.async.wait_group 1;");
        else             asm volatile("cp.async.wait_group 0;");
        __syncthreads();
        const int s = kt % 3;
        const float* as = Asm + s * A_STAGE;
        const float* bs = Bsm + s * B_STAGE;

#pragma unroll
        for (int kk = 0; kk < BK2; kk += 8) {
            unsigned af[4][4], bf[8][2];
#pragma unroll
            for (int mt = 0; mt < 4; mt++) {
                int r = wm + mt * 16 + gid;
                af[mt][0] = tf32rna(as[r * ASTR + kk + tid4]);
                af[mt][1] = tf32rna(as[(r + 8) * ASTR + kk + tid4]);
                af[mt][2] = tf32rna(as[r * ASTR + kk + tid4 + 4]);
                af[mt][3] = tf32rna(as[(r + 8) * ASTR + kk + tid4 + 4]);
            }
#pragma unroll
            for (int nt = 0; nt < 8; nt++) {
                int c = wn + nt * 8 + gid;
                bf[nt][0] = __float_as_uint(bs[c * ASTR + kk + tid4]);
                bf[nt][1] = __float_as_uint(bs[c * ASTR + kk + tid4 + 4]);
            }
#pragma unroll
            for (int mt = 0; mt < 4; mt++)
#pragma unroll
                for (int nt = 0; nt < 8; nt++) {
                    asm volatile(
                        "mma.sync.aligned.m16n8k8.row.col.f32.tf32.tf32.f32 "
                        "{%0,%1,%2,%3}, {%4,%5,%6,%7}, {%8,%9}, {%0,%1,%2,%3};"
                        : "+f"(acc[mt][nt][0]), "+f"(acc[mt][nt][1]),
                          "+f"(acc[mt][nt][2]), "+f"(acc[mt][nt][3])
                        : "r"(af[mt][0]), "r"(af[mt][1]),
                          "r"(af[mt][2]), "r"(af[mt][3]),
                          "r"(bf[nt][0]), "r"(bf[nt][1]));
                }
        }
        if (kt + 2 < NT) load_stage((kt + 2) % 3, (kt + 2) * BK2);
    }

#pragma unroll
    for (int mt = 0; mt < 4; mt++) {
        int r1 = m0 + wm + mt * 16 + gid;
        int r2 = r1 + 8;
#pragma unroll
        for (int nt = 0; nt < 8; nt++) {
            int c = n0 + wn + nt * 8 + tid4 * 2;
            if (r1 < NN) *(float2*)(g_h1 + (size_t)r1 * HC + c) =
                make_float2(acc[mt][nt][0], acc[mt][nt][1]);
            if (r2 < NN) *(float2*)(g_h1 + (size_t)r2 * HC + c) =
                make_float2(acc[mt][nt][2], acc[mt][nt][3]);
        }
    }
}

// ---------------- per-node attention logits (layer 1) ------------------------
__global__ void alpha1_kernel(const float* __restrict__ asrc,
                              const float* __restrict__ adst) {
    int warp = (blockIdx.x * blockDim.x + threadIdx.x) >> 5;
    int lane = threadIdx.x & 31;
    if (warp >= NN) return;
    const float* row = g_h1 + (size_t)warp * HC;
    float ps[HEADS], pd[HEADS];
#pragma unroll
    for (int h = 0; h < HEADS; h++) { ps[h] = 0.f; pd[h] = 0.f; }
#pragma unroll
    for (int h = 0; h < HEADS; h++)
#pragma unroll
        for (int j = 0; j < 4; j++) {
            int idx = (h * 4 + j) * 32 + lane;
            float v = row[idx];
            ps[h] += v * asrc[idx];
            pd[h] += v * adst[idx];
        }
#pragma unroll
    for (int off = 16; off; off >>= 1)
#pragma unroll
        for (int h = 0; h < HEADS; h++) {
            ps[h] += __shfl_xor_sync(0xffffffffu, ps[h], off);
            pd[h] += __shfl_xor_sync(0xffffffffu, pd[h], off);
        }
    if (lane == 0)
#pragma unroll
        for (int h = 0; h < HEADS; h++) {
            g_as1[warp * HEADS + h] = ps[h];
            g_ad1[warp * HEADS + h] = pd[h];
        }
}

// ------- fused layer-1 softmax + aggregate + ELU + GEMM2 partial ------------
// 4 warps per dst node (one head each). Result accumulated into g_h2 atomics.
__global__ __launch_bounds__(256) void fused_agg1(const float* __restrict__ b1,
                                                  const float* __restrict__ W2) {
    int gw   = (blockIdx.x * blockDim.x + threadIdx.x) >> 5;
    int lane = threadIdx.x & 31;
    int d    = gw >> 2;
    int h    = gw & 3;
    if (d >= NN) return;
    const int beg = g_off[d], end = g_off[d + 1];
    const int deg = end - beg;
    const float ad = g_ad1[d * 4 + h];
    const float4* hbase = (const float4*)g_h1;

    float den;
    float4 a = {0.f, 0.f, 0.f, 0.f};

    if (deg <= 32) {
        int   s_l = (lane < deg) ? g_esrc[beg + lane] : 0;
        float e_l = (lane < deg) ? lrelu(g_as1[s_l * 4 + h] + ad) : -1e30f;
        float m = e_l;
#pragma unroll
        for (int off = 16; off; off >>= 1)
            m = fmaxf(m, __shfl_xor_sync(0xffffffffu, m, off));
        float w_l = (lane < deg) ? __expf(e_l - m) : 0.f;
        den = w_l;
#pragma unroll
        for (int off = 16; off; off >>= 1)
            den += __shfl_xor_sync(0xffffffffu, den, off);
#pragma unroll 8
        for (int j = 0; j < deg; j++) {
            float w = __shfl_sync(0xffffffffu, w_l, j);
            int   s = __shfl_sync(0xffffffffu, s_l, j);
            float4 v = hbase[(size_t)s * 128 + h * 32 + lane];
            a.x += w * v.x; a.y += w * v.y; a.z += w * v.z; a.w += w * v.w;
        }
    } else {
        float m = -1e30f;
        for (int i = beg + lane; i < end; i += 32)
            m = fmaxf(m, lrelu(g_as1[g_esrc[i] * 4 + h] + ad));
#pragma unroll
        for (int off = 16; off; off >>= 1)
            m = fmaxf(m, __shfl_xor_sync(0xffffffffu, m, off));
        den = 0.f;
        for (int base = beg; base < end; base += 32) {
            int   idx = base + lane;
            int   s_l = (idx < end) ? g_esrc[idx] : 0;
            float w_l = (idx < end)
                      ? __expf(lrelu(g_as1[s_l * 4 + h] + ad) - m) : 0.f;
            den += w_l;
            int n = min(32, end - base);
#pragma unroll 8
            for (int j = 0; j < n; j++) {
                float w = __shfl_sync(0xffffffffu, w_l, j);
                int   s = __shfl_sync(0xffffffffu, s_l, j);
                float4 v = hbase[(size_t)s * 128 + h * 32 + lane];
                a.x += w * v.x; a.y += w * v.y; a.z += w * v.z; a.w += w * v.w;
            }
        }
#pragma unroll
        for (int off = 16; off; off >>= 1)
            den += __shfl_xor_sync(0xffffffffu, den, off);
    }
    const float r = 1.f / den;
    float vv[4] = {a.x * r, a.y * r, a.z * r, a.w * r};

    // ELU(. + b1) then 128x6 slice of GEMM2, reduced across warp
    float part[CLS];
#pragma unroll
    for (int c = 0; c < CLS; c++) part[c] = 0.f;
    const int kbase = h * 128 + lane * 4;
#pragma unroll
    for (int j = 0; j < 4; j++) {
        int k = kbase + j;
        float act = vv[j] + b1[k];
        act = act > 0.f ? act : (__expf(act) - 1.f);
#pragma unroll
        for (int c = 0; c < CLS; c++) part[c] += act * W2[k * CLS + c];
    }
#pragma unroll
    for (int off = 16; off; off >>= 1)
#pragma unroll
        for (int c = 0; c < CLS; c++)
            part[c] += __shfl_xor_sync(0xffffffffu, part[c], off);
    if (lane == 0)
#pragma unroll
        for (int c = 0; c < CLS; c++)
            atomicAdd(&g_h2[d * CLS + c], part[c]);
}

// ------------- layer-2 logits: one thread per node ---------------------------
__global__ void alpha2_kernel(const float* __restrict__ asrc2,
                              const float* __restrict__ adst2) {
    int i = blockIdx.x * blockDim.x + threadIdx.x;
    if (i >= NN) return;
    float s2 = 0.f, d2 = 0.f;
#pragma unroll
    for (int c = 0; c < CLS; c++) {
        float v = g_h2[i * CLS + c];
        s2 += v * asrc2[c];
        d2 += v * adst2[c];
    }
    g_as2[i] = s2;
    g_ad2[i] = d2;
}

// ------------- fused layer-2 softmax + aggregate ----------------------------
__global__ __launch_bounds__(256) void fused_agg2(const float* __restrict__ b2,
                                                  float* __restrict__ out) {
    int d    = (blockIdx.x * blockDim.x + threadIdx.x) >> 5;
    int lane = threadIdx.x & 31;
    if (d >= NN) return;
    const int beg = g_off[d], end = g_off[d + 1];
    const float ad = g_ad2[d];

    float m = -1e30f;
    for (int i = beg + lane; i < end; i += 32)
        m = fmaxf(m, lrelu(g_as2[g_esrc[i]] + ad));
#pragma unroll
    for (int off = 16; off; off >>= 1)
        m = fmaxf(m, __shfl_xor_sync(0xffffffffu, m, off));

    float den = 0.f;
    float acc[CLS];
#pragma unroll
    for (int c = 0; c < CLS; c++) acc[c] = 0.f;
    for (int i = beg + lane; i < end; i += 32) {
        int s = g_esrc[i];
        float w = __expf(lrelu(g_as2[s] + ad) - m);
        den += w;
#pragma unroll
        for (int c = 0; c < CLS; c++) acc[c] += w * g_h2[s * CLS + c];
    }
#pragma unroll
    for (int off = 16; off; off >>= 1) {
        den += __shfl_xor_sync(0xffffffffu, den, off);
#pragma unroll
        for (int c = 0; c < CLS; c++)
            acc[c] += __shfl_xor_sync(0xffffffffu, acc[c], off);
    }
    if (lane == 0) {
        float rden = 1.f / den;
#pragma unroll
        for (int c = 0; c < CLS; c++)
            out[d * CLS + c] = acc[c] * rden + b2[c];
    }
}

// ---------------- launch ----------------------------------------------------
extern "C" void kernel_launch(void* const* d_in, const int* in_sizes, int n_in,
                              void* d_out, int out_size) {
    const float* x     = (const float*)d_in[0];
    const int*   ei    = (const int*)d_in[1];
    const float* W1    = (const float*)d_in[2];
    const float* asrc1 = (const float*)d_in[3];
    const float* adst1 = (const float*)d_in[4];
    const float* b1    = (const float*)d_in[5];
    const float* W2    = (const float*)d_in[6];
    const float* asrc2 = (const float*)d_in[7];
    const float* adst2 = (const float*)d_in[8];
    const float* b2    = (const float*)d_in[9];
    float* out = (float*)d_out;

    static cudaStream_t s2 = nullptr;
    static cudaEvent_t  e1 = nullptr, e2 = nullptr;
    if (!s2) {
        cudaStreamCreateWithFlags(&s2, cudaStreamNonBlocking);
        cudaEventCreateWithFlags(&e1, cudaEventDisableTiming);
        cudaEventCreateWithFlags(&e2, cudaEventDisableTiming);
        cudaFuncSetAttribute(gemm1_tc,
                             cudaFuncAttributeMaxDynamicSharedMemorySize, SMEM_BYTES);
    }

    // fork: CSR build + h2 zero on side stream, overlapped with w1t + GEMM
    cudaEventRecord(e1, 0);
    cudaStreamWaitEvent(s2, e1, 0);
    zero_deg_kernel<<<(NN * CLS + 255) / 256, 256, 0, s2>>>();
    count_kernel<<<(ET + 255) / 256, 256, 0, s2>>>(ei);
    scan_kernel<<<1, 1024, 0, s2>>>();
    scatter_kernel<<<(ET + 255) / 256, 256, 0, s2>>>(ei);
    cudaEventRecord(e2, s2);

    w1t_kernel<<<dim3(HC / 32, FIN / 32), 256>>>(W1);
    gemm1_tc<<<dim3(HC / BN, (NN + BM - 1) / BM), 256, SMEM_BYTES>>>(x);
    alpha1_kernel<<<(NN * 32 + 255) / 256, 256>>>(asrc1, adst1);

    // join: aggregation needs CSR + logits (+ zeroed h2)
    cudaStreamWaitEvent(0, e2, 0);
    fused_agg1<<<(NN * 128 + 255) / 256, 256>>>(b1, W2);
    alpha2_kernel<<<(NN + 255) / 256, 256>>>(asrc2, adst2);
    fused_agg2<<<(NN * 32 + 255) / 256, 256>>>(b2, out);
}